// round 1
// baseline (speedup 1.0000x reference)
#include <cuda_runtime.h>

#define D    4096
#define TPB  256
#define VPT  16            // values per thread (4 x float4)
#define NWARP (TPB / 32)

__global__ __launch_bounds__(TPB)
void entmax_bisect_kernel(const float* __restrict__ X, float* __restrict__ Y) {
    const int row  = blockIdx.x;
    const size_t base = (size_t)row * D;
    const int tid  = threadIdx.x;
    const int lane = tid & 31;
    const int wid  = tid >> 5;

    __shared__ float s_a[NWARP];
    __shared__ float s_b[NWARP];
    __shared__ float s_scal[2];   // [0] = final t, [1] = sum

    // ---- Load row, Xs = (alpha-1)*X = 0.5f*X (exact in fp32) ----
    const float4* Xv = reinterpret_cast<const float4*>(X + base);
    float xs[VPT];
    #pragma unroll
    for (int k = 0; k < 4; k++) {
        float4 f = Xv[k * TPB + tid];       // fully coalesced 128B per warp
        xs[4*k+0] = 0.5f * f.x;
        xs[4*k+1] = 0.5f * f.y;
        xs[4*k+2] = 0.5f * f.z;
        xs[4*k+3] = 0.5f * f.w;
    }

    // ---- Top-2 reduction (exact order statistics, no rounding) ----
    float hi = xs[0];
    float lo = -3.402823466e38f;
    #pragma unroll
    for (int i = 1; i < VPT; i++) {
        float a  = xs[i];
        float nh = fmaxf(hi, a);
        lo = fmaxf(lo, fminf(hi, a));
        hi = nh;
    }
    #pragma unroll
    for (int off = 16; off > 0; off >>= 1) {
        float ohi = __shfl_down_sync(0xffffffffu, hi, off);
        float olo = __shfl_down_sync(0xffffffffu, lo, off);
        float nh  = fmaxf(hi, ohi);
        lo = fmaxf(fmaxf(lo, olo), fminf(hi, ohi));
        hi = nh;
    }
    if (lane == 0) { s_a[wid] = hi; s_b[wid] = lo; }
    __syncthreads();

    // ---- Scalar 50-iteration bisection (thread 0) ----
    // mask = (sum(Z)-1 >= 0). Since u^p in [0.975, 1] for all positive fp32 u,
    // mask <=> (count of Xs_j > t) >= 2, except count==1 where sum = powf(u1,p)
    // which can round to exactly 1.0f only when u1 > ~0.9999 (guard at 0.999f).
    if (tid == 0) {
        float H = s_a[0], L = s_b[0];
        #pragma unroll
        for (int w = 1; w < NWARP; w++) {
            float ohi = s_a[w], olo = s_b[w];
            float nh  = fmaxf(H, ohi);
            L = fmaxf(fmaxf(L, olo), fminf(H, ohi));
            H = nh;
        }
        const float p = (float)(1.0 / 4095.0);   // 1/(d-1), reproduced faithfully
        float t_min = H - 1.0f;                  // m - 1
        float t_max = H - 0.015625f;             // m - d^(1-alpha) = m - 4096^-0.5
        float diff  = t_max - t_min;
        float t     = t_min;
        #pragma unroll 1
        for (int it = 0; it < 50; it++) {
            diff *= 0.5f;                        // diff = diff / 2 (exact)
            t = t_min + diff;                    // same fp32 op as reference
            bool mask;
            if (t < L) {
                mask = true;                     // >=2 positives -> sum >= 1.95
            } else {
                float u1 = H - t;                // single positive element
                mask = (u1 >= 0.999f) ? (powf(u1, p) >= 1.0f) : false;
            }
            if (mask) t_min = t;
        }
        s_scal[0] = t;                           // reference uses last-iteration t
    }
    __syncthreads();

    const float t = s_scal[0];
    const float p = (float)(1.0 / 4095.0);

    // ---- Final Z and row sum (only ~1-3 lanes per row hit powf) ----
    float lsum = 0.0f;
    #pragma unroll
    for (int i = 0; i < VPT; i++) {
        float u = xs[i] - t;
        float z = 0.0f;
        if (u > 0.0f) z = powf(u, p);
        xs[i] = z;
        lsum += z;
    }
    #pragma unroll
    for (int off = 16; off > 0; off >>= 1)
        lsum += __shfl_down_sync(0xffffffffu, lsum, off);
    if (lane == 0) s_a[wid] = lsum;
    __syncthreads();
    if (tid == 0) {
        float S = 0.0f;
        #pragma unroll
        for (int w = 0; w < NWARP; w++) S += s_a[w];
        s_scal[1] = S;
    }
    __syncthreads();

    const float rinv = 1.0f / s_scal[1];         // S > 0 always (count >= 1)

    // ---- Normalize + store (zeros stay exactly zero) ----
    float4* Yv = reinterpret_cast<float4*>(Y + base);
    #pragma unroll
    for (int k = 0; k < 4; k++) {
        float4 o;
        o.x = xs[4*k+0] * rinv;
        o.y = xs[4*k+1] * rinv;
        o.z = xs[4*k+2] * rinv;
        o.w = xs[4*k+3] * rinv;
        Yv[k * TPB + tid] = o;
    }
}

extern "C" void kernel_launch(void* const* d_in, const int* in_sizes, int n_in,
                              void* d_out, int out_size) {
    const float* X = (const float*)d_in[0];
    float* Y = (float*)d_out;
    const int rows = in_sizes[0] / D;            // 8*2048 = 16384
    entmax_bisect_kernel<<<rows, TPB>>>(X, Y);
}